// round 3
// baseline (speedup 1.0000x reference)
#include <cuda_runtime.h>
#include <math.h>

#define BATCH   2
#define SEQ     2048
#define DIM     2048
#define HEADS   16
#define HDIM    128
#define MTOT    (BATCH*SEQ)          /* 4096 */
#define SCALE   0.08838834764831845f /* 1/sqrt(128) */

/* ---- scratch (static device arrays; no allocation allowed) ---- */
__device__ float g_q[BATCH*HEADS*SEQ*HDIM];   /* [b][h][s][d]  33.5MB */
__device__ float g_k[BATCH*HEADS*SEQ*HDIM];
__device__ float g_v[BATCH*HEADS*SEQ*HDIM];
__device__ float g_o[BATCH*SEQ*HEADS*HDIM];   /* [b][s][h*d]   33.5MB */

/* ===================================================================
 * GEMM 1: qkv = X[4096,2048] @ Wqkv[6144,2048]^T
 * 128x128 block tile, 16 k-tile, 8x8 micro-tile, DOUBLE-BUFFERED smem:
 * prefetch next k-tile to regs before compute, store to alternate
 * buffer during compute, ONE __syncthreads per iteration.
 * Epilogue scatters into g_q/g_k/g_v with [b][h][s][d] layout.
 * =================================================================== */
__global__ __launch_bounds__(256, 2)
void gemm_qkv_kernel(const float* __restrict__ X, const float* __restrict__ W)
{
    __shared__ float As[2][16][132];
    __shared__ float Bs[2][16][132];

    const int tid = threadIdx.x;
    const int tx  = tid & 15;        /* n dir */
    const int ty  = tid >> 4;        /* m dir */
    const int mBase = blockIdx.y << 7;
    const int nTile = blockIdx.x;
    const int nBase = nTile << 7;

    float acc[8][8] = {};

    const int lrow = tid >> 2;          /* 0..63 */
    const int lk   = (tid & 3) << 2;    /* 0,4,8,12 */
    const float* Ag = X + (size_t)(mBase + lrow) * DIM + lk;
    const float* Bg = W + (size_t)(nBase + lrow) * DIM + lk;

    /* prologue: load k-tile 0 into buffer 0 */
    {
        float4 a0 = *(const float4*)(Ag);
        float4 a1 = *(const float4*)(Ag + (size_t)64 * DIM);
        float4 b0 = *(const float4*)(Bg);
        float4 b1 = *(const float4*)(Bg + (size_t)64 * DIM);
        As[0][lk+0][lrow] = a0.x; As[0][lk+1][lrow] = a0.y;
        As[0][lk+2][lrow] = a0.z; As[0][lk+3][lrow] = a0.w;
        As[0][lk+0][lrow+64] = a1.x; As[0][lk+1][lrow+64] = a1.y;
        As[0][lk+2][lrow+64] = a1.z; As[0][lk+3][lrow+64] = a1.w;
        Bs[0][lk+0][lrow] = b0.x; Bs[0][lk+1][lrow] = b0.y;
        Bs[0][lk+2][lrow] = b0.z; Bs[0][lk+3][lrow] = b0.w;
        Bs[0][lk+0][lrow+64] = b1.x; Bs[0][lk+1][lrow+64] = b1.y;
        Bs[0][lk+2][lrow+64] = b1.z; Bs[0][lk+3][lrow+64] = b1.w;
    }
    __syncthreads();

    int buf = 0;
    for (int k0 = 0; k0 < DIM; k0 += 16) {
        const int kn = k0 + 16;
        float4 a0, a1, b0, b1;
        if (kn < DIM) {                 /* prefetch next tile to regs */
            a0 = *(const float4*)(Ag + kn);
            a1 = *(const float4*)(Ag + (size_t)64 * DIM + kn);
            b0 = *(const float4*)(Bg + kn);
            b1 = *(const float4*)(Bg + (size_t)64 * DIM + kn);
        }

        #pragma unroll
        for (int kk = 0; kk < 16; kk++) {
            float a[8], b[8];
            *(float4*)(a)   = *(const float4*)&As[buf][kk][ty*8];
            *(float4*)(a+4) = *(const float4*)&As[buf][kk][ty*8+4];
            *(float4*)(b)   = *(const float4*)&Bs[buf][kk][tx*8];
            *(float4*)(b+4) = *(const float4*)&Bs[buf][kk][tx*8+4];
            #pragma unroll
            for (int i = 0; i < 8; i++)
                #pragma unroll
                for (int j = 0; j < 8; j++)
                    acc[i][j] = fmaf(a[i], b[j], acc[i][j]);
        }

        if (kn < DIM) {                 /* fill alternate buffer */
            const int nb = buf ^ 1;
            As[nb][lk+0][lrow] = a0.x; As[nb][lk+1][lrow] = a0.y;
            As[nb][lk+2][lrow] = a0.z; As[nb][lk+3][lrow] = a0.w;
            As[nb][lk+0][lrow+64] = a1.x; As[nb][lk+1][lrow+64] = a1.y;
            As[nb][lk+2][lrow+64] = a1.z; As[nb][lk+3][lrow+64] = a1.w;
            Bs[nb][lk+0][lrow] = b0.x; Bs[nb][lk+1][lrow] = b0.y;
            Bs[nb][lk+2][lrow] = b0.z; Bs[nb][lk+3][lrow] = b0.w;
            Bs[nb][lk+0][lrow+64] = b1.x; Bs[nb][lk+1][lrow+64] = b1.y;
            Bs[nb][lk+2][lrow+64] = b1.z; Bs[nb][lk+3][lrow+64] = b1.w;
        }
        __syncthreads();
        buf ^= 1;
    }

    /* epilogue: n-tile -> (which, head); d = tx*8 + j */
    const int which = nTile >> 4;      /* 0=q 1=k 2=v */
    const int head  = nTile & 15;
    float* base = (which == 0) ? g_q : ((which == 1) ? g_k : g_v);

    #pragma unroll
    for (int i = 0; i < 8; i++) {
        int m = mBase + ty*8 + i;
        int b = m >> 11;               /* /SEQ */
        int s = m & 2047;
        float* dst = base + ((size_t)((b*HEADS + head)*SEQ + s))*HDIM + tx*8;
        *(float4*)(dst)   = make_float4(acc[i][0], acc[i][1], acc[i][2], acc[i][3]);
        *(float4*)(dst+4) = make_float4(acc[i][4], acc[i][5], acc[i][6], acc[i][7]);
    }
}

/* ===================================================================
 * GEMM 2 (output proj): out = O[4096,2048] @ Wout[2048,2048]^T
 * Same double-buffered scheme.
 * =================================================================== */
__global__ __launch_bounds__(256, 2)
void gemm_out_kernel(const float* __restrict__ W, float* __restrict__ Out)
{
    __shared__ float As[2][16][132];
    __shared__ float Bs[2][16][132];

    const int tid = threadIdx.x;
    const int tx  = tid & 15;
    const int ty  = tid >> 4;
    const int mBase = blockIdx.y << 7;
    const int nBase = blockIdx.x << 7;

    float acc[8][8] = {};

    const int lrow = tid >> 2;
    const int lk   = (tid & 3) << 2;
    const float* Ag = g_o + (size_t)(mBase + lrow) * DIM + lk;
    const float* Bg = W   + (size_t)(nBase + lrow) * DIM + lk;

    {
        float4 a0 = *(const float4*)(Ag);
        float4 a1 = *(const float4*)(Ag + (size_t)64 * DIM);
        float4 b0 = *(const float4*)(Bg);
        float4 b1 = *(const float4*)(Bg + (size_t)64 * DIM);
        As[0][lk+0][lrow] = a0.x; As[0][lk+1][lrow] = a0.y;
        As[0][lk+2][lrow] = a0.z; As[0][lk+3][lrow] = a0.w;
        As[0][lk+0][lrow+64] = a1.x; As[0][lk+1][lrow+64] = a1.y;
        As[0][lk+2][lrow+64] = a1.z; As[0][lk+3][lrow+64] = a1.w;
        Bs[0][lk+0][lrow] = b0.x; Bs[0][lk+1][lrow] = b0.y;
        Bs[0][lk+2][lrow] = b0.z; Bs[0][lk+3][lrow] = b0.w;
        Bs[0][lk+0][lrow+64] = b1.x; Bs[0][lk+1][lrow+64] = b1.y;
        Bs[0][lk+2][lrow+64] = b1.z; Bs[0][lk+3][lrow+64] = b1.w;
    }
    __syncthreads();

    int buf = 0;
    for (int k0 = 0; k0 < DIM; k0 += 16) {
        const int kn = k0 + 16;
        float4 a0, a1, b0, b1;
        if (kn < DIM) {
            a0 = *(const float4*)(Ag + kn);
            a1 = *(const float4*)(Ag + (size_t)64 * DIM + kn);
            b0 = *(const float4*)(Bg + kn);
            b1 = *(const float4*)(Bg + (size_t)64 * DIM + kn);
        }

        #pragma unroll
        for (int kk = 0; kk < 16; kk++) {
            float a[8], b[8];
            *(float4*)(a)   = *(const float4*)&As[buf][kk][ty*8];
            *(float4*)(a+4) = *(const float4*)&As[buf][kk][ty*8+4];
            *(float4*)(b)   = *(const float4*)&Bs[buf][kk][tx*8];
            *(float4*)(b+4) = *(const float4*)&Bs[buf][kk][tx*8+4];
            #pragma unroll
            for (int i = 0; i < 8; i++)
                #pragma unroll
                for (int j = 0; j < 8; j++)
                    acc[i][j] = fmaf(a[i], b[j], acc[i][j]);
        }

        if (kn < DIM) {
            const int nb = buf ^ 1;
            As[nb][lk+0][lrow] = a0.x; As[nb][lk+1][lrow] = a0.y;
            As[nb][lk+2][lrow] = a0.z; As[nb][lk+3][lrow] = a0.w;
            As[nb][lk+0][lrow+64] = a1.x; As[nb][lk+1][lrow+64] = a1.y;
            As[nb][lk+2][lrow+64] = a1.z; As[nb][lk+3][lrow+64] = a1.w;
            Bs[nb][lk+0][lrow] = b0.x; Bs[nb][lk+1][lrow] = b0.y;
            Bs[nb][lk+2][lrow] = b0.z; Bs[nb][lk+3][lrow] = b0.w;
            Bs[nb][lk+0][lrow+64] = b1.x; Bs[nb][lk+1][lrow+64] = b1.y;
            Bs[nb][lk+2][lrow+64] = b1.z; Bs[nb][lk+3][lrow+64] = b1.w;
        }
        __syncthreads();
        buf ^= 1;
    }

    #pragma unroll
    for (int i = 0; i < 8; i++) {
        float* dst = Out + (size_t)(mBase + ty*8 + i) * DIM + nBase + tx*8;
        *(float4*)(dst)   = make_float4(acc[i][0], acc[i][1], acc[i][2], acc[i][3]);
        *(float4*)(dst+4) = make_float4(acc[i][4], acc[i][5], acc[i][6], acc[i][7]);
    }
}

/* ===================================================================
 * Flash attention: per (b,h, 64-row q tile). 64-row kv tiles.
 * Online softmax (m,l,alpha in smem). V reuses the K smem buffer.
 * Thread layout 16x16:
 *   S tile: rows ty*4+i, cols tx+16*j  (4x4 per thread)
 *   O tile: rows ty*4+i, cols tx*8+c   (4x8 per thread)
 * =================================================================== */
#define QS_STRIDE 132
#define PS_STRIDE 68
#define ATTN_SMEM ((64*QS_STRIDE*2 + 64*PS_STRIDE + 3*64) * 4)

__global__ __launch_bounds__(256, 2)
void attn_kernel()
{
    extern __shared__ float sm[];
    float* Qs = sm;                        /* 64 x 132 */
    float* Ks = Qs + 64*QS_STRIDE;         /* 64 x 132 (K, then reused for V) */
    float* Ps = Ks + 64*QS_STRIDE;         /* 64 x 68  */
    float* mS = Ps + 64*PS_STRIDE;
    float* lS = mS + 64;
    float* aS = lS + 64;

    const int tid = threadIdx.x;
    const int tx  = tid & 15;
    const int ty  = tid >> 4;
    const int qBase = blockIdx.x << 6;
    const int bh = blockIdx.y;
    const size_t headOff = (size_t)bh * SEQ * HDIM;
    const float* Qg = g_q + headOff;
    const float* Kg = g_k + headOff;
    const float* Vg = g_v + headOff;

    /* load Q tile (2048 float4 / 256 threads = 8 each) */
    #pragma unroll
    for (int i = 0; i < 8; i++) {
        int f = tid + (i << 8);
        int row = f >> 5;
        int c = (f & 31) << 2;
        *(float4*)&Qs[row*QS_STRIDE + c] =
            *(const float4*)&Qg[(size_t)(qBase + row)*HDIM + c];
    }
    if (tid < 64) { mS[tid] = -1e30f; lS[tid] = 0.0f; }

    float o[4][8] = {};

    for (int kt = 0; kt < SEQ/64; kt++) {
        const int kBase = kt << 6;
        __syncthreads();   /* protect Ks reuse (prev O-update / first-iter Q) */

        /* load K tile */
        #pragma unroll
        for (int i = 0; i < 8; i++) {
            int f = tid + (i << 8);
            int row = f >> 5;
            int c = (f & 31) << 2;
            *(float4*)&Ks[row*QS_STRIDE + c] =
                *(const float4*)&Kg[(size_t)(kBase + row)*HDIM + c];
        }
        __syncthreads();

        /* S = Q K^T  (4 rows x 4 strided cols per thread) */
        float s[4][4] = {};
        #pragma unroll 4
        for (int k = 0; k < HDIM; k += 4) {
            float4 qv[4], kv[4];
            #pragma unroll
            for (int i = 0; i < 4; i++)
                qv[i] = *(const float4*)&Qs[(ty*4 + i)*QS_STRIDE + k];
            #pragma unroll
            for (int j = 0; j < 4; j++)
                kv[j] = *(const float4*)&Ks[(tx + 16*j)*QS_STRIDE + k];
            #pragma unroll
            for (int i = 0; i < 4; i++)
                #pragma unroll
                for (int j = 0; j < 4; j++) {
                    s[i][j] = fmaf(qv[i].x, kv[j].x, s[i][j]);
                    s[i][j] = fmaf(qv[i].y, kv[j].y, s[i][j]);
                    s[i][j] = fmaf(qv[i].z, kv[j].z, s[i][j]);
                    s[i][j] = fmaf(qv[i].w, kv[j].w, s[i][j]);
                }
        }
        #pragma unroll
        for (int i = 0; i < 4; i++)
            #pragma unroll
            for (int j = 0; j < 4; j++)
                Ps[(ty*4 + i)*PS_STRIDE + tx + 16*j] = s[i][j] * SCALE;
        __syncthreads();   /* Ps ready; Ks no longer read for K */

        /* load V into the K buffer */
        #pragma unroll
        for (int i = 0; i < 8; i++) {
            int f = tid + (i << 8);
            int row = f >> 5;
            int c = (f & 31) << 2;
            *(float4*)&Ks[row*QS_STRIDE + c] =
                *(const float4*)&Vg[(size_t)(kBase + row)*HDIM + c];
        }

        /* online softmax: one thread per row */
        if (tid < 64) {
            float* pr = Ps + tid*PS_STRIDE;
            float mOld = mS[tid];
            float mx = mOld;
            #pragma unroll 8
            for (int j = 0; j < 64; j++) mx = fmaxf(mx, pr[j]);
            float alpha = __expf(mOld - mx);
            float sum = 0.0f;
            #pragma unroll 8
            for (int j = 0; j < 64; j++) {
                float p = __expf(pr[j] - mx);
                pr[j] = p;
                sum += p;
            }
            lS[tid] = lS[tid]*alpha + sum;
            mS[tid] = mx;
            aS[tid] = alpha;
        }
        __syncthreads();   /* V + softmax done */

        /* O update: o = o*alpha + P V */
        #pragma unroll
        for (int i = 0; i < 4; i++) {
            float al = aS[ty*4 + i];
            #pragma unroll
            for (int c = 0; c < 8; c++) o[i][c] *= al;
        }
        #pragma unroll 2
        for (int j = 0; j < 64; j += 4) {
            float pl[4][4];
            #pragma unroll
            for (int i = 0; i < 4; i++) {
                float4 t = *(const float4*)&Ps[(ty*4 + i)*PS_STRIDE + j];
                pl[i][0] = t.x; pl[i][1] = t.y; pl[i][2] = t.z; pl[i][3] = t.w;
            }
            #pragma unroll
            for (int jj = 0; jj < 4; jj++) {
                float4 v0 = *(const float4*)&Ks[(j + jj)*QS_STRIDE + tx*8];
                float4 v1 = *(const float4*)&Ks[(j + jj)*QS_STRIDE + tx*8 + 4];
                #pragma unroll
                for (int i = 0; i < 4; i++) {
                    float p = pl[i][jj];
                    o[i][0] = fmaf(p, v0.x, o[i][0]);
                    o[i][1] = fmaf(p, v0.y, o[i][1]);
                    o[i][2] = fmaf(p, v0.z, o[i][2]);
                    o[i][3] = fmaf(p, v0.w, o[i][3]);
                    o[i][4] = fmaf(p, v1.x, o[i][4]);
                    o[i][5] = fmaf(p, v1.y, o[i][5]);
                    o[i][6] = fmaf(p, v1.z, o[i][6]);
                    o[i][7] = fmaf(p, v1.w, o[i][7]);
                }
            }
        }
    }

    /* finalize: o / l, store to g_o[b][s][h*d] */
    const int b = bh >> 4;
    const int h = bh & 15;
    #pragma unroll
    for (int i = 0; i < 4; i++) {
        int r = ty*4 + i;
        float inv = 1.0f / lS[r];
        float* dst = g_o + ((size_t)(b*SEQ + qBase + r)*HEADS + h)*HDIM + tx*8;
        *(float4*)(dst)   = make_float4(o[i][0]*inv, o[i][1]*inv, o[i][2]*inv, o[i][3]*inv);
        *(float4*)(dst+4) = make_float4(o[i][4]*inv, o[i][5]*inv, o[i][6]*inv, o[i][7]*inv);
    }
}

/* =================================================================== */
extern "C" void kernel_launch(void* const* d_in, const int* in_sizes, int n_in,
                              void* d_out, int out_size)
{
    const float* x     = (const float*)d_in[0];
    const float* w_qkv = (const float*)d_in[1];
    const float* w_out = (const float*)d_in[2];
    float* out = (float*)d_out;

    (void)in_sizes; (void)n_in; (void)out_size;

    cudaFuncSetAttribute(attn_kernel,
                         cudaFuncAttributeMaxDynamicSharedMemorySize, ATTN_SMEM);

    gemm_qkv_kernel<<<dim3(48, 32), 256>>>(x, w_qkv);
    attn_kernel<<<dim3(SEQ/64, BATCH*HEADS), 256, ATTN_SMEM>>>();
    gemm_out_kernel<<<dim3(16, 32), 256>>>(w_out, out);
}

// round 6
// speedup vs baseline: 1.5785x; 1.5785x over previous
#include <cuda_runtime.h>
#include <cuda_bf16.h>
#include <math.h>
#include <stdint.h>

#define BATCH   2
#define SEQ     2048
#define DIM     2048
#define HEADS   16
#define HDIM    128
#define SCALE   0.08838834764831845f /* 1/sqrt(128) */

/* ---- scratch (static device arrays; no allocation allowed) ---- */
__device__ float g_q[BATCH*HEADS*SEQ*HDIM];   /* [b][h][s][d] */
__device__ float g_k[BATCH*HEADS*SEQ*HDIM];
__device__ float g_v[BATCH*HEADS*SEQ*HDIM];
__device__ float g_o[BATCH*SEQ*HEADS*HDIM];   /* [b][s][h*d] */

/* =================== mma.sync helpers (compute_103-safe) =================== */
__device__ __forceinline__ void mma_bf16(float* c, const uint32_t* a, const uint32_t* b) {
    asm volatile("mma.sync.aligned.m16n8k16.row.col.f32.bf16.bf16.f32 "
                 "{%0,%1,%2,%3}, {%4,%5,%6,%7}, {%8,%9}, {%0,%1,%2,%3};"
                 : "+f"(c[0]), "+f"(c[1]), "+f"(c[2]), "+f"(c[3])
                 : "r"(a[0]), "r"(a[1]), "r"(a[2]), "r"(a[3]), "r"(b[0]), "r"(b[1]));
}
__device__ __forceinline__ uint32_t pack_bf16(__nv_bfloat16 lo, __nv_bfloat16 hi) {
    __nv_bfloat162 p = __halves2bfloat162(lo, hi);   /* lo -> .x (low half) */
    return *(uint32_t*)&p;
}

/* ============== bf16x3 GEMM tile machinery ==============
 * Block tile 128x128, K-chunk 32, 8 warps, warp tile 32x64.
 * smem per buffer (32KB): Ahi@0, Alo@8K, Bhi@16K, Blo@24K — FRAGMENT-ORDERED:
 *   A 16x16 bf16 tile = 512B: thread lane reads uint4 at lane*16 = {a0,a1,a2,a3}
 *   B 16x8  bf16 tile = 256B: thread lane reads uint2 at lane*8  = {b0,b1}
 * Double buffered: 64KB total.
 */
#define BUF_STRIDE 32768
#define OFF_ALO    8192
#define OFF_BHI    16384
#define OFF_BLO    24576
#define GEMM_SMEM  65536

__device__ __forceinline__ void fetch_tiles(float4 va[4], float4 vb[4],
                                            const float* __restrict__ A,
                                            const float* __restrict__ B,
                                            int mBase, int nBase, int k0, int tid)
{
    #pragma unroll
    for (int i = 0; i < 4; i++) {
        int f = i * 256 + tid;
        int r = f >> 3, q = f & 7;
        va[i] = *(const float4*)(A + (size_t)(mBase + r) * DIM + k0 + q * 4);
        vb[i] = *(const float4*)(B + (size_t)(nBase + r) * DIM + k0 + q * 4);
    }
}

__device__ __forceinline__ void split_store(const float4 va[4], const float4 vb[4],
                                            char* buf, int tid)
{
    #pragma unroll
    for (int i = 0; i < 4; i++) {
        int f = i * 256 + tid;
        int r = f >> 3, q = f & 7;
        int c0 = q * 4;
        /* ---- A element (r, c0..c0+3), fragment-ordered ---- */
        {
            int mt = r >> 4, rr = r & 15, kt = c0 >> 4, cc = c0 & 15;
            int addr = (((mt * 2 + kt) * 32) + ((rr & 7) * 4 + ((cc >> 1) & 3))) * 16
                     + ((rr >> 3) + ((cc >> 3) << 1)) * 4;
            float4 v = va[i];
            __nv_bfloat16 h0 = __float2bfloat16(v.x), h1 = __float2bfloat16(v.y);
            __nv_bfloat16 h2 = __float2bfloat16(v.z), h3 = __float2bfloat16(v.w);
            *(uint32_t*)(buf + addr)      = pack_bf16(h0, h1);
            *(uint32_t*)(buf + addr + 16) = pack_bf16(h2, h3);
            __nv_bfloat16 l0 = __float2bfloat16(v.x - __bfloat162float(h0));
            __nv_bfloat16 l1 = __float2bfloat16(v.y - __bfloat162float(h1));
            __nv_bfloat16 l2 = __float2bfloat16(v.z - __bfloat162float(h2));
            __nv_bfloat16 l3 = __float2bfloat16(v.w - __bfloat162float(h3));
            *(uint32_t*)(buf + OFF_ALO + addr)      = pack_bf16(l0, l1);
            *(uint32_t*)(buf + OFF_ALO + addr + 16) = pack_bf16(l2, l3);
        }
        /* ---- B element (n=r, k=c0..c0+3), fragment-ordered ---- */
        {
            int nt = r >> 3, nn = r & 7, kt = c0 >> 4, kk = c0 & 15;
            int addr = (((nt * 2 + kt) * 32) + (nn * 4 + ((kk >> 1) & 3))) * 8
                     + (kk >> 3) * 4;
            float4 v = vb[i];
            __nv_bfloat16 h0 = __float2bfloat16(v.x), h1 = __float2bfloat16(v.y);
            __nv_bfloat16 h2 = __float2bfloat16(v.z), h3 = __float2bfloat16(v.w);
            *(uint32_t*)(buf + OFF_BHI + addr)     = pack_bf16(h0, h1);
            *(uint32_t*)(buf + OFF_BHI + addr + 8) = pack_bf16(h2, h3);
            __nv_bfloat16 l0 = __float2bfloat16(v.x - __bfloat162float(h0));
            __nv_bfloat16 l1 = __float2bfloat16(v.y - __bfloat162float(h1));
            __nv_bfloat16 l2 = __float2bfloat16(v.z - __bfloat162float(h2));
            __nv_bfloat16 l3 = __float2bfloat16(v.w - __bfloat162float(h3));
            *(uint32_t*)(buf + OFF_BLO + addr)     = pack_bf16(l0, l1);
            *(uint32_t*)(buf + OFF_BLO + addr + 8) = pack_bf16(l2, l3);
        }
    }
}

/* full K mainloop: result in c[2][8][4] register fragments */
__device__ __forceinline__ void bf16x3_gemm(const float* __restrict__ A,
                                            const float* __restrict__ B,
                                            int mBase, int nBase,
                                            char* smc, float c[2][8][4], int tid)
{
    const int lane = tid & 31, w = tid >> 5, wm = w & 3, wn = w >> 2;

    float4 va[4], vb[4];
    fetch_tiles(va, vb, A, B, mBase, nBase, 0, tid);
    split_store(va, vb, smc, tid);
    __syncthreads();

    for (int ch = 0; ch < 64; ch++) {
        char* cur = smc + (ch & 1) * BUF_STRIDE;
        if (ch < 63)
            fetch_tiles(va, vb, A, B, mBase, nBase, (ch + 1) << 5, tid);

        #pragma unroll
        for (int kt = 0; kt < 2; kt++) {
            uint4 ah[2], al[2];
            #pragma unroll
            for (int m2 = 0; m2 < 2; m2++) {
                int t = (((wm * 2 + m2) * 2 + kt) * 32 + lane) * 16;
                ah[m2] = *(const uint4*)(cur + t);
                al[m2] = *(const uint4*)(cur + OFF_ALO + t);
            }
            #pragma unroll
            for (int n2 = 0; n2 < 8; n2++) {
                int t = (((wn * 8 + n2) * 2 + kt) * 32 + lane) * 8;
                uint2 bh = *(const uint2*)(cur + OFF_BHI + t);
                uint2 bl = *(const uint2*)(cur + OFF_BLO + t);
                #pragma unroll
                for (int m2 = 0; m2 < 2; m2++) {
                    mma_bf16(c[m2][n2], (const uint32_t*)&ah[m2], (const uint32_t*)&bh);
                    mma_bf16(c[m2][n2], (const uint32_t*)&ah[m2], (const uint32_t*)&bl);
                    mma_bf16(c[m2][n2], (const uint32_t*)&al[m2], (const uint32_t*)&bh);
                }
            }
        }

        if (ch < 63)
            split_store(va, vb, smc + ((ch + 1) & 1) * BUF_STRIDE, tid);
        __syncthreads();
    }
}

/* =================== GEMM 1: qkv projection =================== */
__global__ __launch_bounds__(256, 1)
void gemm_qkv_kernel(const float* __restrict__ X, const float* __restrict__ W)
{
    extern __shared__ char smc[];
    const int tid = threadIdx.x;
    const int nTile = blockIdx.x;
    const int mBase = blockIdx.y << 7;
    const int nBase = nTile << 7;

    float c[2][8][4] = {};
    bf16x3_gemm(X, W, mBase, nBase, smc, c, tid);

    const int lane = tid & 31, w = tid >> 5, wm = w & 3, wn = w >> 2;
    const int g = lane >> 2, tig = lane & 3;
    const int which = nTile >> 4;      /* 0=q 1=k 2=v */
    const int head  = nTile & 15;
    float* base = (which == 0) ? g_q : ((which == 1) ? g_k : g_v);

    #pragma unroll
    for (int m2 = 0; m2 < 2; m2++) {
        int m0 = mBase + wm * 32 + m2 * 16 + g;
        #pragma unroll
        for (int n2 = 0; n2 < 8; n2++) {
            int d = wn * 64 + n2 * 8 + tig * 2;
            int b0 = m0 >> 11, s0 = m0 & 2047;
            float* p0 = base + ((size_t)((b0 * HEADS + head) * SEQ + s0)) * HDIM + d;
            *(float2*)p0 = make_float2(c[m2][n2][0], c[m2][n2][1]);
            int m1 = m0 + 8;
            int b1 = m1 >> 11, s1 = m1 & 2047;
            float* p1 = base + ((size_t)((b1 * HEADS + head) * SEQ + s1)) * HDIM + d;
            *(float2*)p1 = make_float2(c[m2][n2][2], c[m2][n2][3]);
        }
    }
}

/* =================== GEMM 2: output projection =================== */
__global__ __launch_bounds__(256, 1)
void gemm_out_kernel(const float* __restrict__ W, float* __restrict__ Out)
{
    extern __shared__ char smc[];
    const int tid = threadIdx.x;
    const int mBase = blockIdx.y << 7;
    const int nBase = blockIdx.x << 7;

    float c[2][8][4] = {};
    bf16x3_gemm(g_o, W, mBase, nBase, smc, c, tid);

    const int lane = tid & 31, w = tid >> 5, wm = w & 3, wn = w >> 2;
    const int g = lane >> 2, tig = lane & 3;

    #pragma unroll
    for (int m2 = 0; m2 < 2; m2++) {
        int m0 = mBase + wm * 32 + m2 * 16 + g;
        #pragma unroll
        for (int n2 = 0; n2 < 8; n2++) {
            int d = nBase + wn * 64 + n2 * 8 + tig * 2;
            float* p0 = Out + (size_t)m0 * DIM + d;
            *(float2*)p0 = make_float2(c[m2][n2][0], c[m2][n2][1]);
            float* p1 = Out + (size_t)(m0 + 8) * DIM + d;
            *(float2*)p1 = make_float2(c[m2][n2][2], c[m2][n2][3]);
        }
    }
}

/* ===================================================================
 * Flash attention (unchanged SIMT path from round 3 — passing)
 * =================================================================== */
#define QS_STRIDE 132
#define PS_STRIDE 68
#define ATTN_SMEM ((64*QS_STRIDE*2 + 64*PS_STRIDE + 3*64) * 4)

__global__ __launch_bounds__(256, 2)
void attn_kernel()
{
    extern __shared__ float sm[];
    float* Qs = sm;
    float* Ks = Qs + 64*QS_STRIDE;
    float* Ps = Ks + 64*QS_STRIDE;
    float* mS = Ps + 64*PS_STRIDE;
    float* lS = mS + 64;
    float* aS = lS + 64;

    const int tid = threadIdx.x;
    const int tx  = tid & 15;
    const int ty  = tid >> 4;
    const int qBase = blockIdx.x << 6;
    const int bh = blockIdx.y;
    const size_t headOff = (size_t)bh * SEQ * HDIM;
    const float* Qg = g_q + headOff;
    const float* Kg = g_k + headOff;
    const float* Vg = g_v + headOff;

    #pragma unroll
    for (int i = 0; i < 8; i++) {
        int f = tid + (i << 8);
        int row = f >> 5;
        int c = (f & 31) << 2;
        *(float4*)&Qs[row*QS_STRIDE + c] =
            *(const float4*)&Qg[(size_t)(qBase + row)*HDIM + c];
    }
    if (tid < 64) { mS[tid] = -1e30f; lS[tid] = 0.0f; }

    float o[4][8] = {};

    for (int kt = 0; kt < SEQ/64; kt++) {
        const int kBase = kt << 6;
        __syncthreads();

        #pragma unroll
        for (int i = 0; i < 8; i++) {
            int f = tid + (i << 8);
            int row = f >> 5;
            int c = (f & 31) << 2;
            *(float4*)&Ks[row*QS_STRIDE + c] =
                *(const float4*)&Kg[(size_t)(kBase + row)*HDIM + c];
        }
        __syncthreads();

        float s[4][4] = {};
        #pragma unroll 4
        for (int k = 0; k < HDIM; k += 4) {
            float4 qv[4], kv[4];
            #pragma unroll
            for (int i = 0; i < 4; i++)
                qv[i] = *(const float4*)&Qs[(ty*4 + i)*QS_STRIDE + k];
            #pragma unroll
            for (int j = 0; j < 4; j++)
                kv[j] = *(const float4*)&Ks[(tx + 16*j)*QS_STRIDE + k];
            #pragma unroll
            for (int i = 0; i < 4; i++)
                #pragma unroll
                for (int j = 0; j < 4; j++) {
                    s[i][j] = fmaf(qv[i].x, kv[j].x, s[i][j]);
                    s[i][j] = fmaf(qv[i].y, kv[j].y, s[i][j]);
                    s[i][j] = fmaf(qv[i].z, kv[j].z, s[i][j]);
                    s[i][j] = fmaf(qv[i].w, kv[j].w, s[i][j]);
                }
        }
        #pragma unroll
        for (int i = 0; i < 4; i++)
            #pragma unroll
            for (int j = 0; j < 4; j++)
                Ps[(ty*4 + i)*PS_STRIDE + tx + 16*j] = s[i][j] * SCALE;
        __syncthreads();

        #pragma unroll
        for (int i = 0; i < 8; i++) {
            int f = tid + (i << 8);
            int row = f >> 5;
            int c = (f & 31) << 2;
            *(float4*)&Ks[row*QS_STRIDE + c] =
                *(const float4*)&Vg[(size_t)(kBase + row)*HDIM + c];
        }

        if (tid < 64) {
            float* pr = Ps + tid*PS_STRIDE;
            float mOld = mS[tid];
            float mx = mOld;
            #pragma unroll 8
            for (int j = 0; j < 64; j++) mx = fmaxf(mx, pr[j]);
            float alpha = __expf(mOld - mx);
            float sum = 0.0f;
            #pragma unroll 8
            for (int j = 0; j < 64; j++) {
                float p = __expf(pr[j] - mx);
                pr[j] = p;
                sum += p;
            }
            lS[tid] = lS[tid]*alpha + sum;
            mS[tid] = mx;
            aS[tid] = alpha;
        }
        __syncthreads();

        #pragma unroll
        for (int i = 0; i < 4; i++) {
            float al = aS[ty*4 + i];
            #pragma unroll
            for (int c = 0; c < 8; c++) o[i][c] *= al;
        }
        #pragma unroll 2
        for (int j = 0; j < 64; j += 4) {
            float pl[4][4];
            #pragma unroll
            for (int i = 0; i < 4; i++) {
                float4 t = *(const float4*)&Ps[(ty*4 + i)*PS_STRIDE + j];
                pl[i][0] = t.x; pl[i][1] = t.y; pl[i][2] = t.z; pl[i][3] = t.w;
            }
            #pragma unroll
            for (int jj = 0; jj < 4; jj++) {
                float4 v0 = *(const float4*)&Ks[(j + jj)*QS_STRIDE + tx*8];
                float4 v1 = *(const float4*)&Ks[(j + jj)*QS_STRIDE + tx*8 + 4];
                #pragma unroll
                for (int i = 0; i < 4; i++) {
                    float p = pl[i][jj];
                    o[i][0] = fmaf(p, v0.x, o[i][0]);
                    o[i][1] = fmaf(p, v0.y, o[i][1]);
                    o[i][2] = fmaf(p, v0.z, o[i][2]);
                    o[i][3] = fmaf(p, v0.w, o[i][3]);
                    o[i][4] = fmaf(p, v1.x, o[i][4]);
                    o[i][5] = fmaf(p, v1.y, o[i][5]);
                    o[i][6] = fmaf(p, v1.z, o[i][6]);
                    o[i][7] = fmaf(p, v1.w, o[i][7]);
                }
            }
        }
    }

    const int b = bh >> 4;
    const int h = bh & 15;
    #pragma unroll
    for (int i = 0; i < 4; i++) {
        int r = ty*4 + i;
        float inv = 1.0f / lS[r];
        float* dst = g_o + ((size_t)(b*SEQ + qBase + r)*HEADS + h)*HDIM + tx*8;
        *(float4*)(dst)   = make_float4(o[i][0]*inv, o[i][1]*inv, o[i][2]*inv, o[i][3]*inv);
        *(float4*)(dst+4) = make_float4(o[i][4]*inv, o[i][5]*inv, o[i][6]*inv, o[i][7]*inv);
    }
}

/* =================================================================== */
extern "C" void kernel_launch(void* const* d_in, const int* in_sizes, int n_in,
                              void* d_out, int out_size)
{
    const float* x     = (const float*)d_in[0];
    const float* w_qkv = (const float*)d_in[1];
    const float* w_out = (const float*)d_in[2];
    float* out = (float*)d_out;

    (void)in_sizes; (void)n_in; (void)out_size;

    cudaFuncSetAttribute(gemm_qkv_kernel,
                         cudaFuncAttributeMaxDynamicSharedMemorySize, GEMM_SMEM);
    cudaFuncSetAttribute(gemm_out_kernel,
                         cudaFuncAttributeMaxDynamicSharedMemorySize, GEMM_SMEM);
    cudaFuncSetAttribute(attn_kernel,
                         cudaFuncAttributeMaxDynamicSharedMemorySize, ATTN_SMEM);

    gemm_qkv_kernel<<<dim3(48, 32), 256, GEMM_SMEM>>>(x, w_qkv);
    attn_kernel<<<dim3(SEQ/64, BATCH*HEADS), 256, ATTN_SMEM>>>();
    gemm_out_kernel<<<dim3(16, 32), 256, GEMM_SMEM>>>(w_out, out);
}

// round 7
// speedup vs baseline: 2.5828x; 1.6362x over previous
#include <cuda_runtime.h>
#include <cuda_bf16.h>
#include <math.h>
#include <stdint.h>

#define BATCH   2
#define SEQ     2048
#define DIM     2048
#define HEADS   16
#define HDIM    128
#define SCALE   0.08838834764831845f /* 1/sqrt(128) */

/* ---- scratch (static device arrays; no allocation allowed) ---- */
__device__ float g_q[BATCH*HEADS*SEQ*HDIM];   /* [b][h][s][d] */
__device__ float g_k[BATCH*HEADS*SEQ*HDIM];
__device__ float g_v[BATCH*HEADS*SEQ*HDIM];   /* TRANSPOSED: [b][h][d][s] */
__device__ float g_o[BATCH*SEQ*HEADS*HDIM];   /* [b][s][h*d] */

/* =================== mma.sync helpers (compute_103-safe) =================== */
__device__ __forceinline__ void mma_bf16(float* c, const uint32_t* a, const uint32_t* b) {
    asm volatile("mma.sync.aligned.m16n8k16.row.col.f32.bf16.bf16.f32 "
                 "{%0,%1,%2,%3}, {%4,%5,%6,%7}, {%8,%9}, {%0,%1,%2,%3};"
                 : "+f"(c[0]), "+f"(c[1]), "+f"(c[2]), "+f"(c[3])
                 : "r"(a[0]), "r"(a[1]), "r"(a[2]), "r"(a[3]), "r"(b[0]), "r"(b[1]));
}
__device__ __forceinline__ uint32_t pack_bf16(__nv_bfloat16 lo, __nv_bfloat16 hi) {
    __nv_bfloat162 p = __halves2bfloat162(lo, hi);   /* lo -> .x (low half) */
    return *(uint32_t*)&p;
}

/* ============== bf16x3 GEMM tile machinery (proven round 6) ============== */
#define BUF_STRIDE 32768
#define OFF_ALO    8192
#define OFF_BHI    16384
#define OFF_BLO    24576
#define GEMM_SMEM  65536

__device__ __forceinline__ void fetch_tiles(float4 va[4], float4 vb[4],
                                            const float* __restrict__ A,
                                            const float* __restrict__ B,
                                            int mBase, int nBase, int k0, int tid)
{
    #pragma unroll
    for (int i = 0; i < 4; i++) {
        int f = i * 256 + tid;
        int r = f >> 3, q = f & 7;
        va[i] = *(const float4*)(A + (size_t)(mBase + r) * DIM + k0 + q * 4);
        vb[i] = *(const float4*)(B + (size_t)(nBase + r) * DIM + k0 + q * 4);
    }
}

__device__ __forceinline__ void split_store(const float4 va[4], const float4 vb[4],
                                            char* buf, int tid)
{
    #pragma unroll
    for (int i = 0; i < 4; i++) {
        int f = i * 256 + tid;
        int r = f >> 3, q = f & 7;
        int c0 = q * 4;
        {   /* A element (r, c0..c0+3), fragment-ordered */
            int mt = r >> 4, rr = r & 15, kt = c0 >> 4, cc = c0 & 15;
            int addr = (((mt * 2 + kt) * 32) + ((rr & 7) * 4 + ((cc >> 1) & 3))) * 16
                     + ((rr >> 3) + ((cc >> 3) << 1)) * 4;
            float4 v = va[i];
            __nv_bfloat16 h0 = __float2bfloat16(v.x), h1 = __float2bfloat16(v.y);
            __nv_bfloat16 h2 = __float2bfloat16(v.z), h3 = __float2bfloat16(v.w);
            *(uint32_t*)(buf + addr)      = pack_bf16(h0, h1);
            *(uint32_t*)(buf + addr + 16) = pack_bf16(h2, h3);
            __nv_bfloat16 l0 = __float2bfloat16(v.x - __bfloat162float(h0));
            __nv_bfloat16 l1 = __float2bfloat16(v.y - __bfloat162float(h1));
            __nv_bfloat16 l2 = __float2bfloat16(v.z - __bfloat162float(h2));
            __nv_bfloat16 l3 = __float2bfloat16(v.w - __bfloat162float(h3));
            *(uint32_t*)(buf + OFF_ALO + addr)      = pack_bf16(l0, l1);
            *(uint32_t*)(buf + OFF_ALO + addr + 16) = pack_bf16(l2, l3);
        }
        {   /* B element (n=r, k=c0..c0+3), fragment-ordered */
            int nt = r >> 3, nn = r & 7, kt = c0 >> 4, kk = c0 & 15;
            int addr = (((nt * 2 + kt) * 32) + (nn * 4 + ((kk >> 1) & 3))) * 8
                     + (kk >> 3) * 4;
            float4 v = vb[i];
            __nv_bfloat16 h0 = __float2bfloat16(v.x), h1 = __float2bfloat16(v.y);
            __nv_bfloat16 h2 = __float2bfloat16(v.z), h3 = __float2bfloat16(v.w);
            *(uint32_t*)(buf + OFF_BHI + addr)     = pack_bf16(h0, h1);
            *(uint32_t*)(buf + OFF_BHI + addr + 8) = pack_bf16(h2, h3);
            __nv_bfloat16 l0 = __float2bfloat16(v.x - __bfloat162float(h0));
            __nv_bfloat16 l1 = __float2bfloat16(v.y - __bfloat162float(h1));
            __nv_bfloat16 l2 = __float2bfloat16(v.z - __bfloat162float(h2));
            __nv_bfloat16 l3 = __float2bfloat16(v.w - __bfloat162float(h3));
            *(uint32_t*)(buf + OFF_BLO + addr)     = pack_bf16(l0, l1);
            *(uint32_t*)(buf + OFF_BLO + addr + 8) = pack_bf16(l2, l3);
        }
    }
}

__device__ __forceinline__ void bf16x3_gemm(const float* __restrict__ A,
                                            const float* __restrict__ B,
                                            int mBase, int nBase,
                                            char* smc, float c[2][8][4], int tid)
{
    const int lane = tid & 31, w = tid >> 5, wm = w & 3, wn = w >> 2;

    float4 va[4], vb[4];
    fetch_tiles(va, vb, A, B, mBase, nBase, 0, tid);
    split_store(va, vb, smc, tid);
    __syncthreads();

    for (int ch = 0; ch < 64; ch++) {
        char* cur = smc + (ch & 1) * BUF_STRIDE;
        if (ch < 63)
            fetch_tiles(va, vb, A, B, mBase, nBase, (ch + 1) << 5, tid);

        #pragma unroll
        for (int kt = 0; kt < 2; kt++) {
            uint4 ah[2], al[2];
            #pragma unroll
            for (int m2 = 0; m2 < 2; m2++) {
                int tt = (((wm * 2 + m2) * 2 + kt) * 32 + lane) * 16;
                ah[m2] = *(const uint4*)(cur + tt);
                al[m2] = *(const uint4*)(cur + OFF_ALO + tt);
            }
            #pragma unroll
            for (int n2 = 0; n2 < 8; n2++) {
                int tt = (((wn * 8 + n2) * 2 + kt) * 32 + lane) * 8;
                uint2 bh = *(const uint2*)(cur + OFF_BHI + tt);
                uint2 bl = *(const uint2*)(cur + OFF_BLO + tt);
                #pragma unroll
                for (int m2 = 0; m2 < 2; m2++) {
                    mma_bf16(c[m2][n2], (const uint32_t*)&ah[m2], (const uint32_t*)&bh);
                    mma_bf16(c[m2][n2], (const uint32_t*)&ah[m2], (const uint32_t*)&bl);
                    mma_bf16(c[m2][n2], (const uint32_t*)&al[m2], (const uint32_t*)&bh);
                }
            }
        }

        if (ch < 63)
            split_store(va, vb, smc + ((ch + 1) & 1) * BUF_STRIDE, tid);
        __syncthreads();
    }
}

/* =================== GEMM 1: qkv projection =================== */
__global__ __launch_bounds__(256, 1)
void gemm_qkv_kernel(const float* __restrict__ X, const float* __restrict__ W)
{
    extern __shared__ char smc[];
    const int tid = threadIdx.x;
    const int nTile = blockIdx.x;
    const int mBase = blockIdx.y << 7;
    const int nBase = nTile << 7;

    float c[2][8][4] = {};
    bf16x3_gemm(X, W, mBase, nBase, smc, c, tid);

    const int lane = tid & 31, w = tid >> 5, wm = w & 3, wn = w >> 2;
    const int g = lane >> 2, tig = lane & 3;
    const int which = nTile >> 4;      /* 0=q 1=k 2=v */
    const int head  = nTile & 15;

    if (which == 2) {
        /* V stored TRANSPOSED: g_v[b][h][d][s] */
        #pragma unroll
        for (int m2 = 0; m2 < 2; m2++) {
            int m0 = mBase + wm * 32 + m2 * 16 + g;
            int b0 = m0 >> 11, s0 = m0 & 2047;
            float* vb = g_v + (size_t)(b0 * HEADS + head) * HDIM * SEQ;
            #pragma unroll
            for (int n2 = 0; n2 < 8; n2++) {
                int d = wn * 64 + n2 * 8 + tig * 2;
                vb[(size_t)d * SEQ + s0]           = c[m2][n2][0];
                vb[(size_t)(d + 1) * SEQ + s0]     = c[m2][n2][1];
                vb[(size_t)d * SEQ + s0 + 8]       = c[m2][n2][2];
                vb[(size_t)(d + 1) * SEQ + s0 + 8] = c[m2][n2][3];
            }
        }
    } else {
        float* base = (which == 0) ? g_q : g_k;
        #pragma unroll
        for (int m2 = 0; m2 < 2; m2++) {
            int m0 = mBase + wm * 32 + m2 * 16 + g;
            #pragma unroll
            for (int n2 = 0; n2 < 8; n2++) {
                int d = wn * 64 + n2 * 8 + tig * 2;
                int b0 = m0 >> 11, s0 = m0 & 2047;
                float* p0 = base + ((size_t)((b0 * HEADS + head) * SEQ + s0)) * HDIM + d;
                *(float2*)p0 = make_float2(c[m2][n2][0], c[m2][n2][1]);
                float* p1 = base + ((size_t)((b0 * HEADS + head) * SEQ + s0 + 8)) * HDIM + d;
                *(float2*)p1 = make_float2(c[m2][n2][2], c[m2][n2][3]);
            }
        }
    }
}

/* =================== GEMM 2: output projection =================== */
__global__ __launch_bounds__(256, 1)
void gemm_out_kernel(const float* __restrict__ W, float* __restrict__ Out)
{
    extern __shared__ char smc[];
    const int tid = threadIdx.x;
    const int mBase = blockIdx.y << 7;
    const int nBase = blockIdx.x << 7;

    float c[2][8][4] = {};
    bf16x3_gemm(g_o, W, mBase, nBase, smc, c, tid);

    const int lane = tid & 31, w = tid >> 5, wm = w & 3, wn = w >> 2;
    const int g = lane >> 2, tig = lane & 3;

    #pragma unroll
    for (int m2 = 0; m2 < 2; m2++) {
        int m0 = mBase + wm * 32 + m2 * 16 + g;
        #pragma unroll
        for (int n2 = 0; n2 < 8; n2++) {
            int d = nBase + wn * 64 + n2 * 8 + tig * 2;
            float* p0 = Out + (size_t)m0 * DIM + d;
            *(float2*)p0 = make_float2(c[m2][n2][0], c[m2][n2][1]);
            float* p1 = Out + (size_t)(m0 + 8) * DIM + d;
            *(float2*)p1 = make_float2(c[m2][n2][2], c[m2][n2][3]);
        }
    }
}

/* ===================================================================
 * Flash attention via bf16x3 mma.sync (FA2-style).
 * CTA: 128 q-rows, 8 warps (warp = 16 rows). kv-tile 64.
 * smem: Q A-frags hi/lo (64K), K B-frags hi/lo (32K), V^T B-frags hi/lo (32K)
 * =================================================================== */
#define A_QHI 0
#define A_QLO 32768
#define A_KHI 65536
#define A_KLO 81920
#define A_VHI 98304
#define A_VLO 114688
#define ATTN_SMEM 131072

__global__ __launch_bounds__(256, 1)
void attn_kernel()
{
    extern __shared__ char smc[];
    const int tid  = threadIdx.x;
    const int lane = tid & 31;
    const int w    = tid >> 5;
    const int g    = lane >> 2;
    const int t    = lane & 3;

    const int qBase = blockIdx.x << 7;
    const int bh    = blockIdx.y;
    const float* Qg = g_q + (size_t)bh * SEQ * HDIM;
    const float* Kg = g_k + (size_t)bh * SEQ * HDIM;
    const float* Vt = g_v + (size_t)bh * HDIM * SEQ;   /* [d][s] */

    /* ---- split Q (pre-scaled) into A-fragment smem, once ---- */
    #pragma unroll
    for (int i = 0; i < 16; i++) {
        int f = i * 256 + tid;
        int r = f >> 5, q = f & 31;
        float4 v = *(const float4*)(Qg + (size_t)(qBase + r) * HDIM + q * 4);
        v.x *= SCALE; v.y *= SCALE; v.z *= SCALE; v.w *= SCALE;
        int mt = r >> 4, rr = r & 15, ktd = q >> 2, cc = (q & 3) * 4;
        int addr = ((mt * 8 + ktd) * 32 + (rr & 7) * 4 + ((cc >> 1) & 3)) * 16
                 + ((rr >> 3) + ((cc >> 3) << 1)) * 4;
        __nv_bfloat16 h0 = __float2bfloat16(v.x), h1 = __float2bfloat16(v.y);
        __nv_bfloat16 h2 = __float2bfloat16(v.z), h3 = __float2bfloat16(v.w);
        *(uint32_t*)(smc + A_QHI + addr)      = pack_bf16(h0, h1);
        *(uint32_t*)(smc + A_QHI + addr + 16) = pack_bf16(h2, h3);
        __nv_bfloat16 l0 = __float2bfloat16(v.x - __bfloat162float(h0));
        __nv_bfloat16 l1 = __float2bfloat16(v.y - __bfloat162float(h1));
        __nv_bfloat16 l2 = __float2bfloat16(v.z - __bfloat162float(h2));
        __nv_bfloat16 l3 = __float2bfloat16(v.w - __bfloat162float(h3));
        *(uint32_t*)(smc + A_QLO + addr)      = pack_bf16(l0, l1);
        *(uint32_t*)(smc + A_QLO + addr + 16) = pack_bf16(l2, l3);
    }

    float m0 = -1e30f, m1 = -1e30f, l0r = 0.0f, l1r = 0.0f;
    float o[16][4] = {};

    for (int kv = 0; kv < SEQ / 64; kv++) {
        const int kvBase = kv << 6;

        /* LDG K tile (64x128) and V^T tile (128x64) into registers */
        float4 kst[8], vst[8];
        #pragma unroll
        for (int i = 0; i < 8; i++) {
            int f = i * 256 + tid;
            int r = f >> 5, q = f & 31;
            kst[i] = *(const float4*)(Kg + (size_t)(kvBase + r) * HDIM + q * 4);
        }
        #pragma unroll
        for (int i = 0; i < 8; i++) {
            int f = i * 256 + tid;
            int r = f >> 4, q = f & 15;
            vst[i] = *(const float4*)(Vt + (size_t)r * SEQ + kvBase + q * 4);
        }

        /* split-store K into B-frag smem (n=s_kv, k=d, 8 k-tiles) */
        #pragma unroll
        for (int i = 0; i < 8; i++) {
            int f = i * 256 + tid;
            int r = f >> 5, q = f & 31;
            int nt = r >> 3, nn = r & 7, ktl = q >> 2, kk = (q & 3) * 4;
            int addr = ((nt * 8 + ktl) * 32 + nn * 4 + ((kk >> 1) & 3)) * 8 + (kk >> 3) * 4;
            float4 v = kst[i];
            __nv_bfloat16 h0 = __float2bfloat16(v.x), h1 = __float2bfloat16(v.y);
            __nv_bfloat16 h2 = __float2bfloat16(v.z), h3 = __float2bfloat16(v.w);
            *(uint32_t*)(smc + A_KHI + addr)     = pack_bf16(h0, h1);
            *(uint32_t*)(smc + A_KHI + addr + 8) = pack_bf16(h2, h3);
            __nv_bfloat16 q0 = __float2bfloat16(v.x - __bfloat162float(h0));
            __nv_bfloat16 q1 = __float2bfloat16(v.y - __bfloat162float(h1));
            __nv_bfloat16 q2 = __float2bfloat16(v.z - __bfloat162float(h2));
            __nv_bfloat16 q3 = __float2bfloat16(v.w - __bfloat162float(h3));
            *(uint32_t*)(smc + A_KLO + addr)     = pack_bf16(q0, q1);
            *(uint32_t*)(smc + A_KLO + addr + 8) = pack_bf16(q2, q3);
        }
        __syncthreads();

        /* ---- S = Q K^T (x3) ---- */
        float s[8][4] = {};
        #pragma unroll
        for (int ktd = 0; ktd < 8; ktd++) {
            uint4 ah = *(const uint4*)(smc + A_QHI + ((w * 8 + ktd) * 32 + lane) * 16);
            uint4 al = *(const uint4*)(smc + A_QLO + ((w * 8 + ktd) * 32 + lane) * 16);
            #pragma unroll
            for (int nt = 0; nt < 8; nt++) {
                uint2 kb = *(const uint2*)(smc + A_KHI + ((nt * 8 + ktd) * 32 + lane) * 8);
                uint2 kl = *(const uint2*)(smc + A_KLO + ((nt * 8 + ktd) * 32 + lane) * 8);
                mma_bf16(s[nt], (const uint32_t*)&ah, (const uint32_t*)&kb);
                mma_bf16(s[nt], (const uint32_t*)&ah, (const uint32_t*)&kl);
                mma_bf16(s[nt], (const uint32_t*)&al, (const uint32_t*)&kb);
            }
        }

        /* ---- online softmax on fragments (rows g and g+8) ---- */
        float mx0 = -1e30f, mx1 = -1e30f;
        #pragma unroll
        for (int nt = 0; nt < 8; nt++) {
            mx0 = fmaxf(mx0, fmaxf(s[nt][0], s[nt][1]));
            mx1 = fmaxf(mx1, fmaxf(s[nt][2], s[nt][3]));
        }
        mx0 = fmaxf(mx0, __shfl_xor_sync(0xffffffffu, mx0, 1));
        mx0 = fmaxf(mx0, __shfl_xor_sync(0xffffffffu, mx0, 2));
        mx1 = fmaxf(mx1, __shfl_xor_sync(0xffffffffu, mx1, 1));
        mx1 = fmaxf(mx1, __shfl_xor_sync(0xffffffffu, mx1, 2));
        float nm0 = fmaxf(m0, mx0), nm1 = fmaxf(m1, mx1);
        float a0 = __expf(m0 - nm0), a1 = __expf(m1 - nm1);
        m0 = nm0; m1 = nm1;

        float sum0 = 0.0f, sum1 = 0.0f;
        uint32_t ph[4][4], pl[4][4];
        #pragma unroll
        for (int nt = 0; nt < 8; nt++) {
            float p0 = __expf(s[nt][0] - nm0);
            float p1 = __expf(s[nt][1] - nm0);
            float p2 = __expf(s[nt][2] - nm1);
            float p3 = __expf(s[nt][3] - nm1);
            sum0 += p0 + p1; sum1 += p2 + p3;
            __nv_bfloat16 h0 = __float2bfloat16(p0), h1 = __float2bfloat16(p1);
            __nv_bfloat16 h2 = __float2bfloat16(p2), h3 = __float2bfloat16(p3);
            int ks = nt >> 1, hf = (nt & 1) << 1;
            ph[ks][hf]     = pack_bf16(h0, h1);
            ph[ks][hf + 1] = pack_bf16(h2, h3);
            __nv_bfloat16 e0 = __float2bfloat16(p0 - __bfloat162float(h0));
            __nv_bfloat16 e1 = __float2bfloat16(p1 - __bfloat162float(h1));
            __nv_bfloat16 e2 = __float2bfloat16(p2 - __bfloat162float(h2));
            __nv_bfloat16 e3 = __float2bfloat16(p3 - __bfloat162float(h3));
            pl[ks][hf]     = pack_bf16(e0, e1);
            pl[ks][hf + 1] = pack_bf16(e2, e3);
        }
        sum0 += __shfl_xor_sync(0xffffffffu, sum0, 1);
        sum0 += __shfl_xor_sync(0xffffffffu, sum0, 2);
        sum1 += __shfl_xor_sync(0xffffffffu, sum1, 1);
        sum1 += __shfl_xor_sync(0xffffffffu, sum1, 2);
        l0r = l0r * a0 + sum0;
        l1r = l1r * a1 + sum1;

        /* rescale O */
        #pragma unroll
        for (int nt = 0; nt < 16; nt++) {
            o[nt][0] *= a0; o[nt][1] *= a0;
            o[nt][2] *= a1; o[nt][3] *= a1;
        }

        /* split-store V^T into B-frag smem (n=d, k=s_kv, 4 k-tiles) */
        #pragma unroll
        for (int i = 0; i < 8; i++) {
            int f = i * 256 + tid;
            int r = f >> 4, q = f & 15;
            int nt = r >> 3, nn = r & 7, ktl = q >> 2, kk = (q & 3) * 4;
            int addr = ((nt * 4 + ktl) * 32 + nn * 4 + ((kk >> 1) & 3)) * 8 + (kk >> 3) * 4;
            float4 v = vst[i];
            __nv_bfloat16 h0 = __float2bfloat16(v.x), h1 = __float2bfloat16(v.y);
            __nv_bfloat16 h2 = __float2bfloat16(v.z), h3 = __float2bfloat16(v.w);
            *(uint32_t*)(smc + A_VHI + addr)     = pack_bf16(h0, h1);
            *(uint32_t*)(smc + A_VHI + addr + 8) = pack_bf16(h2, h3);
            __nv_bfloat16 q0 = __float2bfloat16(v.x - __bfloat162float(h0));
            __nv_bfloat16 q1 = __float2bfloat16(v.y - __bfloat162float(h1));
            __nv_bfloat16 q2 = __float2bfloat16(v.z - __bfloat162float(h2));
            __nv_bfloat16 q3 = __float2bfloat16(v.w - __bfloat162float(h3));
            *(uint32_t*)(smc + A_VLO + addr)     = pack_bf16(q0, q1);
            *(uint32_t*)(smc + A_VLO + addr + 8) = pack_bf16(q2, q3);
        }
        __syncthreads();

        /* ---- O += P V (x3) ---- */
        #pragma unroll
        for (int ks = 0; ks < 4; ks++) {
            #pragma unroll
            for (int nt = 0; nt < 16; nt++) {
                uint2 vb = *(const uint2*)(smc + A_VHI + ((nt * 4 + ks) * 32 + lane) * 8);
                uint2 vl = *(const uint2*)(smc + A_VLO + ((nt * 4 + ks) * 32 + lane) * 8);
                mma_bf16(o[nt], ph[ks], (const uint32_t*)&vb);
                mma_bf16(o[nt], ph[ks], (const uint32_t*)&vl);
                mma_bf16(o[nt], pl[ks], (const uint32_t*)&vb);
            }
        }
    }

    /* ---- finalize: O /= l, write g_o[b][s][h*d] ---- */
    float inv0 = 1.0f / l0r, inv1 = 1.0f / l1r;
    int row0 = qBase + w * 16 + g;
    int b = bh >> 4, h = bh & 15;
    float* d0 = g_o + ((size_t)(b * SEQ + row0) * HEADS + h) * HDIM;
    float* d1 = g_o + ((size_t)(b * SEQ + row0 + 8) * HEADS + h) * HDIM;
    #pragma unroll
    for (int nt = 0; nt < 16; nt++) {
        int d = nt * 8 + t * 2;
        *(float2*)(d0 + d) = make_float2(o[nt][0] * inv0, o[nt][1] * inv0);
        *(float2*)(d1 + d) = make_float2(o[nt][2] * inv1, o[nt][3] * inv1);
    }
}

/* =================================================================== */
extern "C" void kernel_launch(void* const* d_in, const int* in_sizes, int n_in,
                              void* d_out, int out_size)
{
    const float* x     = (const float*)d_in[0];
    const float* w_qkv = (const float*)d_in[1];
    const float* w_out = (const float*)d_in[2];
    float* out = (float*)d_out;

    (void)in_sizes; (void)n_in; (void)out_size;

    cudaFuncSetAttribute(gemm_qkv_kernel,
                         cudaFuncAttributeMaxDynamicSharedMemorySize, GEMM_SMEM);
    cudaFuncSetAttribute(gemm_out_kernel,
                         cudaFuncAttributeMaxDynamicSharedMemorySize, GEMM_SMEM);
    cudaFuncSetAttribute(attn_kernel,
                         cudaFuncAttributeMaxDynamicSharedMemorySize, ATTN_SMEM);

    gemm_qkv_kernel<<<dim3(48, 32), 256, GEMM_SMEM>>>(x, w_qkv);
    attn_kernel<<<dim3(SEQ/128, BATCH*HEADS), 256, ATTN_SMEM>>>();
    gemm_out_kernel<<<dim3(16, 32), 256, GEMM_SMEM>>>(w_out, out);
}